// round 4
// baseline (speedup 1.0000x reference)
#include <cuda_runtime.h>
#include <cstdint>

// Problem constants
constexpr int D_   = 64;      // item dim
constexpr int L_   = 16;      // code length
constexpr int NB_  = 65536;   // buckets

// Tiling
constexpr int BLOCK_ = 128;           // threads per block (4 warps -> all SMSPs)
constexpr int M_     = 4;             // items per thread
constexpr int TILE_  = BLOCK_ * M_;   // 512 items per block
constexpr int KST_   = 4;             // k-stages
constexpr int KS_    = D_ / KST_;     // 16 floats per row per stage
constexpr int STAGE_F4_ = TILE_ * (KS_ / 4);   // 2048 float4 per stage

// ---------------- f32x2 helpers (sm_103a packed fp32) ----------------
__device__ __forceinline__ uint64_t dup_f32(float x) {
    uint64_t r;
    asm("mov.b64 %0, {%1, %1};" : "=l"(r) : "f"(x));
    return r;
}
__device__ __forceinline__ void fma2(uint64_t& acc, uint64_t a, uint64_t b) {
    asm("fma.rn.f32x2 %0, %1, %2, %0;" : "+l"(acc) : "l"(a), "l"(b));
}
__device__ __forceinline__ void unpack2(uint64_t v, float& lo, float& hi) {
    asm("mov.b64 {%0, %1}, %2;" : "=f"(lo), "=f"(hi) : "l"(v));
}
__device__ __forceinline__ void cp_async16(void* smem_dst, const void* gsrc) {
    unsigned s = (unsigned)__cvta_generic_to_shared(smem_dst);
    asm volatile("cp.async.cg.shared.global [%0], [%1], 16;" :: "r"(s), "l"(gsrc));
}
__device__ __forceinline__ void cp_commit() {
    asm volatile("cp.async.commit_group;" ::: "memory");
}
template<int N>
__device__ __forceinline__ void cp_wait() {
    asm volatile("cp.async.wait_group %0;" :: "n"(N) : "memory");
}

// ---------------- counts init (d_out is poisoned; seed from input counts) ----
__global__ void init_counts_kernel(float* __restrict__ outCounts,
                                   const float* __restrict__ counts, int nb) {
    int i = blockIdx.x * blockDim.x + threadIdx.x;
    if (i < nb) outCounts[i] = counts[i];
}

// ---------------- main kernel ----------------
__global__ __launch_bounds__(BLOCK_, 3)
void hash_counter_kernel(const float* __restrict__ items,
                         const float* __restrict__ W,
                         float* __restrict__ outBuckets,
                         float* __restrict__ outCounts,
                         int n, int asInt) {
    // Stage layout: row r occupies 16 floats (64 B) at r*16; chunk c (16 B)
    // sits at 16B-unit (r*4 + (c ^ ((r>>1)&3))). This XOR swizzle is
    // conflict-free for both the coalesced cp.async stores and the
    // row-strided float4 reads.
    __shared__ float sIt[2][TILE_ * KS_];  // 2 x 32 KB
    __shared__ float sW[D_ * L_];          // W_hash row-major [64][16] (4 KB)

    const int tid = threadIdx.x;
    const long base = (long)blockIdx.x * TILE_;
    const float* gbase = items + base * D_;

    // ---- stage loader: cols [s*16, s*16+16) of all TILE_ rows ----
    auto load_stage = [&](int s, int buf) {
        #pragma unroll
        for (int i = 0; i < STAGE_F4_ / BLOCK_; ++i) {     // 16 iters
            int idx = tid + i * BLOCK_;                    // float4 idx in stage
            int row = idx >> 2;
            int c   = idx & 3;
            int u   = row * 4 + (c ^ ((row >> 1) & 3));    // swizzled 16B unit
            if (base + row < n)
                cp_async16(&sIt[buf][u * 4],
                           gbase + (size_t)row * D_ + s * KS_ + c * 4);
        }
    };

    // Prologue: group0 = W + stage0, group1 = stage1
    #pragma unroll
    for (int i = 0; i < (D_ * L_ / 4) / BLOCK_; ++i) {     // 2 iters
        int idx = tid + i * BLOCK_;
        cp_async16(&sW[idx * 4], W + idx * 4);
    }
    load_stage(0, 0);
    cp_commit();
    load_stage(1, 1);
    cp_commit();

    // Accumulators: acc[m][j] = (dot_{2j}, dot_{2j+1})
    uint64_t acc[M_][8];
    #pragma unroll
    for (int m = 0; m < M_; ++m)
        #pragma unroll
        for (int j = 0; j < 8; ++j) acc[m][j] = 0ull;

    #pragma unroll
    for (int s = 0; s < KST_; ++s) {
        if (s < KST_ - 1) cp_wait<1>(); else cp_wait<0>();
        __syncthreads();
        const int buf = s & 1;

        #pragma unroll
        for (int c = 0; c < 4; ++c) {                      // 4-k chunk in stage
            float4 v[M_];
            #pragma unroll
            for (int m = 0; m < M_; ++m) {
                int r = tid + m * BLOCK_;
                int u = r * 4 + (c ^ ((r >> 1) & 3));
                v[m] = *reinterpret_cast<const float4*>(&sIt[buf][u * 4]);
            }
            #pragma unroll
            for (int kk = 0; kk < 4; ++kk) {
                const int k = s * KS_ + c * 4 + kk;
                const ulonglong2* wr =
                    reinterpret_cast<const ulonglong2*>(&sW[k * L_]);
                ulonglong2 wA = wr[0], wB = wr[1], wC = wr[2], wD = wr[3];
                uint64_t wq[8] = {wA.x, wA.y, wB.x, wB.y, wC.x, wC.y, wD.x, wD.y};
                #pragma unroll
                for (int m = 0; m < M_; ++m) {
                    float vk = (kk == 0) ? v[m].x : (kk == 1) ? v[m].y
                             : (kk == 2) ? v[m].z : v[m].w;
                    uint64_t dv = dup_f32(vk);
                    #pragma unroll
                    for (int j = 0; j < 8; ++j) fma2(acc[m][j], dv, wq[j]);
                }
            }
        }

        __syncthreads();                                   // all done reading buf
        if (s + 2 < KST_) {                                // prefetch s+2 into buf
            load_stage(s + 2, buf);
            cp_commit();
        }
    }

    // Sign bits -> bucket; write + histogram
    #pragma unroll
    for (int m = 0; m < M_; ++m) {
        long gi = base + tid + m * BLOCK_;
        if (gi < n) {
            unsigned b = 0;
            #pragma unroll
            for (int j = 0; j < 8; ++j) {
                float lo, hi;
                unpack2(acc[m][j], lo, hi);
                if (lo >= 0.0f) b |= 1u << (15 - 2 * j);
                if (hi >= 0.0f) b |= 1u << (14 - 2 * j);
            }
            if (outBuckets) {
                if (asInt) reinterpret_cast<int*>(outBuckets)[gi] = (int)b;
                else       outBuckets[gi] = (float)b;
            }
            if (outCounts) atomicAdd(&outCounts[b], 1.0f);
        }
    }
}

// ---------------- launch ----------------
extern "C" void kernel_launch(void* const* d_in, const int* in_sizes, int n_in,
                              void* d_out, int out_size) {
    const float* items  = (const float*)d_in[0];
    const float* W      = (const float*)d_in[1];
    const float* counts = (const float*)d_in[2];
    const int n = in_sizes[0] / D_;

    float* out = (float*)d_out;
    float* outBuckets = nullptr;
    float* outCounts  = nullptr;
    int asInt = 0;

    if (out_size >= n + NB_) {           // expected: concatenated (buckets, counts) as f32
        outBuckets = out;
        outCounts  = out + n;
    } else if (out_size == NB_) {        // counts only
        outCounts = out;
    } else {                             // buckets only -> keep reference dtype (int32)
        outBuckets = out;
        asInt = 1;
    }

    if (outCounts)
        init_counts_kernel<<<(NB_ + 255) / 256, 256>>>(outCounts, counts, NB_);

    const int grid = (n + TILE_ - 1) / TILE_;
    hash_counter_kernel<<<grid, BLOCK_>>>(items, W, outBuckets, outCounts, n, asInt);
}

// round 5
// speedup vs baseline: 1.5020x; 1.5020x over previous
#include <cuda_runtime.h>
#include <cstdint>

// Problem constants
constexpr int D_   = 64;      // item dim
constexpr int L_   = 16;      // code length
constexpr int NB_  = 65536;   // buckets

// Tiling
constexpr int BLOCK_ = 64;            // threads per block
constexpr int M_     = 4;             // items per thread
constexpr int TILE_  = BLOCK_ * M_;   // 256 items per block
constexpr int HALF_  = TILE_ / 2;     // 128 rows per commit group

// ---------------- f32x2 helpers (sm_103a packed fp32) ----------------
__device__ __forceinline__ uint64_t dup_f32(float x) {
    uint64_t r;
    asm("mov.b64 %0, {%1, %1};" : "=l"(r) : "f"(x));
    return r;
}
__device__ __forceinline__ void fma2(uint64_t& acc, uint64_t a, uint64_t b) {
    asm("fma.rn.f32x2 %0, %1, %2, %0;" : "+l"(acc) : "l"(a), "l"(b));
}
__device__ __forceinline__ void unpack2(uint64_t v, float& lo, float& hi) {
    asm("mov.b64 {%0, %1}, %2;" : "=f"(lo), "=f"(hi) : "l"(v));
}
__device__ __forceinline__ void cp_async16(void* smem_dst, const void* gsrc) {
    unsigned s = (unsigned)__cvta_generic_to_shared(smem_dst);
    asm volatile("cp.async.cg.shared.global [%0], [%1], 16;" :: "r"(s), "l"(gsrc));
}
__device__ __forceinline__ void cp_commit() {
    asm volatile("cp.async.commit_group;" ::: "memory");
}
template<int N>
__device__ __forceinline__ void cp_wait() {
    asm volatile("cp.async.wait_group %0;" :: "n"(N) : "memory");
}

// ---------------- counts init (d_out is poisoned; seed from input counts) ----
__global__ void init_counts_kernel(float* __restrict__ outCounts,
                                   const float* __restrict__ counts, int nb) {
    int i = blockIdx.x * blockDim.x + threadIdx.x;
    if (i < nb) outCounts[i] = counts[i];
}

// ---------------- main kernel ----------------
__global__ __launch_bounds__(BLOCK_)
void hash_counter_kernel(const float* __restrict__ items,
                         const float* __restrict__ W,
                         float* __restrict__ outBuckets,
                         float* __restrict__ outCounts,
                         int n, int asInt) {
    // Item tile: 256 rows x 64 floats (256B/row), XOR-swizzled 16B chunks:
    // chunk c of row r lives at float offset r*64 + ((c ^ (r & 15)) * 4).
    // Conflict-free for both coalesced cp.async stores and strided reads.
    __shared__ float sIt[TILE_ * D_];      // 65,536 B
    __shared__ float sW[D_ * L_];          // W_hash row-major [64][16] (4 KB)

    const int tid = threadIdx.x;
    const long base = (long)blockIdx.x * TILE_;
    const float* gbase = items + base * D_;

    // ---- group 0: W + rows [0, 128) ----
    #pragma unroll
    for (int i = 0; i < (D_ * L_ / 4) / BLOCK_; ++i) {     // 2 iters
        int idx = tid + i * BLOCK_;
        cp_async16(&sW[idx * 4], W + idx * 4);
    }
    #pragma unroll
    for (int i = 0; i < HALF_ * (D_ / 4) / BLOCK_; ++i) {  // 32 iters
        int idx = tid + i * BLOCK_;                        // float4 idx, rows 0..127
        int row = idx >> 4;
        int col = idx & 15;
        int scol = col ^ (row & 15);
        if (base + row < n)
            cp_async16(&sIt[row * D_ + scol * 4], gbase + (size_t)idx * 4);
    }
    cp_commit();
    // ---- group 1: rows [128, 256) ----
    #pragma unroll
    for (int i = 0; i < HALF_ * (D_ / 4) / BLOCK_; ++i) {  // 32 iters
        int idx = HALF_ * (D_ / 4) + tid + i * BLOCK_;     // rows 128..255
        int row = idx >> 4;
        int col = idx & 15;
        int scol = col ^ (row & 15);
        if (base + row < n)
            cp_async16(&sIt[row * D_ + scol * 4], gbase + (size_t)idx * 4);
    }
    cp_commit();

    // ---- two passes: pass p covers items m = 2p, 2p+1 (rows tid+2p*64, tid+(2p+1)*64)
    #pragma unroll
    for (int p = 0; p < 2; ++p) {
        if (p == 0) cp_wait<1>(); else cp_wait<0>();
        __syncthreads();

        uint64_t acc[2][8];
        #pragma unroll
        for (int mm = 0; mm < 2; ++mm)
            #pragma unroll
            for (int j = 0; j < 8; ++j) acc[mm][j] = 0ull;

        #pragma unroll 4
        for (int c = 0; c < 16; ++c) {                     // k-chunk of 4
            float4 v[2];
            #pragma unroll
            for (int mm = 0; mm < 2; ++mm) {
                int r = tid + (2 * p + mm) * BLOCK_;
                int scol = c ^ (r & 15);
                v[mm] = *reinterpret_cast<const float4*>(&sIt[r * D_ + scol * 4]);
            }
            #pragma unroll
            for (int kk = 0; kk < 4; ++kk) {
                const int k = c * 4 + kk;
                const ulonglong2* wr =
                    reinterpret_cast<const ulonglong2*>(&sW[k * L_]);
                ulonglong2 wA = wr[0], wB = wr[1], wC = wr[2], wD = wr[3];
                uint64_t wq[8] = {wA.x, wA.y, wB.x, wB.y, wC.x, wC.y, wD.x, wD.y};
                #pragma unroll
                for (int mm = 0; mm < 2; ++mm) {
                    float vk = (kk == 0) ? v[mm].x : (kk == 1) ? v[mm].y
                             : (kk == 2) ? v[mm].z : v[mm].w;
                    uint64_t dv = dup_f32(vk);
                    #pragma unroll
                    for (int j = 0; j < 8; ++j) fma2(acc[mm][j], dv, wq[j]);
                }
            }
        }

        // Sign bits -> bucket; write + histogram (2 items of this pass)
        #pragma unroll
        for (int mm = 0; mm < 2; ++mm) {
            long gi = base + tid + (2 * p + mm) * BLOCK_;
            if (gi < n) {
                unsigned b = 0;
                #pragma unroll
                for (int j = 0; j < 8; ++j) {
                    float lo, hi;
                    unpack2(acc[mm][j], lo, hi);
                    if (lo >= 0.0f) b |= 1u << (15 - 2 * j);
                    if (hi >= 0.0f) b |= 1u << (14 - 2 * j);
                }
                if (outBuckets) {
                    if (asInt) reinterpret_cast<int*>(outBuckets)[gi] = (int)b;
                    else       outBuckets[gi] = (float)b;
                }
                if (outCounts) atomicAdd(&outCounts[b], 1.0f);
            }
        }
    }
}

// ---------------- launch ----------------
extern "C" void kernel_launch(void* const* d_in, const int* in_sizes, int n_in,
                              void* d_out, int out_size) {
    const float* items  = (const float*)d_in[0];
    const float* W      = (const float*)d_in[1];
    const float* counts = (const float*)d_in[2];
    const int n = in_sizes[0] / D_;

    float* out = (float*)d_out;
    float* outBuckets = nullptr;
    float* outCounts  = nullptr;
    int asInt = 0;

    if (out_size >= n + NB_) {           // expected: concatenated (buckets, counts) as f32
        outBuckets = out;
        outCounts  = out + n;
    } else if (out_size == NB_) {        // counts only
        outCounts = out;
    } else {                             // buckets only -> keep reference dtype (int32)
        outBuckets = out;
        asInt = 1;
    }

    if (outCounts)
        init_counts_kernel<<<(NB_ + 255) / 256, 256>>>(outCounts, counts, NB_);

    const int grid = (n + TILE_ - 1) / TILE_;
    hash_counter_kernel<<<grid, BLOCK_>>>(items, W, outBuckets, outCounts, n, asInt);
}

// round 6
// speedup vs baseline: 1.5696x; 1.0450x over previous
#include <cuda_runtime.h>
#include <cstdint>

// Problem constants
constexpr int D_   = 64;      // item dim
constexpr int L_   = 16;      // code length
constexpr int NB_  = 65536;   // buckets

// Tiling
constexpr int BLOCK_ = 64;               // 2 warps
constexpr int WARPS_ = BLOCK_ / 32;
constexpr int M_     = 4;                // items per thread
constexpr int ROWSW_ = 32 * M_;          // 128 rows per warp
constexpr int TILE_  = ROWSW_ * WARPS_;  // 256 rows per block-tile
constexpr int KS_    = 16;               // k per stage (64 B per row-stage)
constexpr int KST_   = D_ / KS_;         // 4 stages
constexpr int STF_   = ROWSW_ * KS_;     // 2048 floats per stage buffer (8 KB)
constexpr int GRID_  = 888;              // 148 SMs x 6 resident blocks

// ---------------- f32x2 helpers ----------------
__device__ __forceinline__ uint64_t dup_f32(float x) {
    uint64_t r; asm("mov.b64 %0, {%1, %1};" : "=l"(r) : "f"(x)); return r;
}
__device__ __forceinline__ void fma2(uint64_t& a, uint64_t b, uint64_t c) {
    asm("fma.rn.f32x2 %0, %1, %2, %0;" : "+l"(a) : "l"(b), "l"(c));
}
__device__ __forceinline__ void unpack2(uint64_t v, float& lo, float& hi) {
    asm("mov.b64 {%0, %1}, %2;" : "=f"(lo), "=f"(hi) : "l"(v));
}
__device__ __forceinline__ void cp_async16(void* d, const void* s) {
    unsigned a = (unsigned)__cvta_generic_to_shared(d);
    asm volatile("cp.async.cg.shared.global [%0], [%1], 16;" :: "r"(a), "l"(s));
}
__device__ __forceinline__ void cp_commit() {
    asm volatile("cp.async.commit_group;" ::: "memory");
}
template<int N>
__device__ __forceinline__ void cp_wait() {
    asm volatile("cp.async.wait_group %0;" :: "n"(N) : "memory");
}

// ---------------- counts init ----------------
__global__ void init_counts_kernel(float* __restrict__ outCounts,
                                   const float* __restrict__ counts, int nb) {
    int i = blockIdx.x * blockDim.x + threadIdx.x;
    if (i < nb) outCounts[i] = counts[i];
}

// ---------------- tail kernel (n % TILE_ items; usually 0 blocks) ----------
__global__ void hash_tail_kernel(const float* __restrict__ items,
                                 const float* __restrict__ W,
                                 float* __restrict__ outBuckets,
                                 float* __restrict__ outCounts,
                                 int start, int n, int asInt) {
    int gi = start + blockIdx.x * blockDim.x + threadIdx.x;
    if (gi >= n) return;
    const float* row = items + (size_t)gi * D_;
    float dot[L_];
    #pragma unroll
    for (int j = 0; j < L_; ++j) dot[j] = 0.0f;
    for (int k = 0; k < D_; ++k) {
        float v = row[k];
        #pragma unroll
        for (int j = 0; j < L_; ++j) dot[j] = fmaf(v, W[k * L_ + j], dot[j]);
    }
    unsigned b = 0;
    #pragma unroll
    for (int j = 0; j < L_; ++j)
        if (dot[j] >= 0.0f) b |= 1u << (L_ - 1 - j);
    if (outBuckets) {
        if (asInt) reinterpret_cast<int*>(outBuckets)[gi] = (int)b;
        else       outBuckets[gi] = (float)b;
    }
    if (outCounts) atomicAdd(&outCounts[b], 1.0f);
}

// ---------------- main kernel ----------------
__global__ __launch_bounds__(BLOCK_)
void hash_counter_kernel(const float* __restrict__ items,
                         const float* __restrict__ W,
                         float* __restrict__ outBuckets,
                         float* __restrict__ outCounts,
                         int nTiles, int asInt) {
    // Per warp: two 8 KB stage buffers. Row r (0..127) stage data: 16 floats,
    // 16B-chunk c stored at unit (r*4 + (c ^ ((r>>1)&3))).
    // Conflict-free for coalesced stores (8 lanes = 2 rows x 4 chunks -> 8 banks)
    // and for consumer reads (8 consecutive rows, fixed c -> 8 banks).
    __shared__ __align__(128) float sIt[WARPS_][2][STF_];
    __shared__ __align__(16)  float sW[D_ * L_];

    const int tid = threadIdx.x;
    const int w   = tid >> 5;
    const int l   = tid & 31;

    // W: 16 floats per thread, once
    for (int i = tid; i < D_ * L_; i += BLOCK_) sW[i] = W[i];
    __syncthreads();

    // ---- hoisted loader constants ----
    // lane l writes float4s idx = l + 32i  ->  row=(l>>2)+8i, c=l&3
    // scol = c ^ ((row>>1)&3) = (l&3) ^ ((l>>3)&3)   (constant per lane)
    const int scolL = (l & 3) ^ ((l >> 3) & 3);
    float* const smL0 = &sIt[w][0][(l >> 2) * KS_ + scolL * 4];

    // ---- hoisted consumer constants ----
    // thread reads rows 32m+l; byte addr = base + 2048m + 64l + 16*(c ^ ((l>>1)&3))
    char* const cb0 = (char*)&sIt[w][0][0];
    unsigned coff[M_];
    {
        const unsigned z = ((unsigned)(l >> 1) & 3u) << 4;
        #pragma unroll
        for (int m = 0; m < M_; ++m)
            coff[m] = (unsigned)(2048 * m + 64 * l) + z;
    }

    uint64_t acc[M_][8];

    const size_t rowOff = (size_t)(w * ROWSW_ + (l >> 2)) * D_ + (l & 3) * 4;

    for (long t = blockIdx.x; t < nTiles; t += GRID_) {
        const float* g = items + (size_t)t * TILE_ * D_ + rowOff;

        // stage loader: 16 cp.asyncs, pointer + immediate only
        auto load_stage = [&](int s, int buf) {
            const float* gs = g + s * KS_;
            float* sm = smL0 + buf * STF_;
            #pragma unroll
            for (int i = 0; i < 16; ++i)
                cp_async16(sm + i * 128, gs + (size_t)i * 8 * D_);
        };

        auto compute_stage = [&](int s, int buf) {
            const char* cbuf = cb0 + buf * (STF_ * 4);
            #pragma unroll
            for (int c = 0; c < 4; ++c) {
                float4 v[M_];
                #pragma unroll
                for (int m = 0; m < M_; ++m)
                    v[m] = *reinterpret_cast<const float4*>(
                               cbuf + (coff[m] ^ (unsigned)(c << 4)));
                #pragma unroll
                for (int kk = 0; kk < 4; ++kk) {
                    const int k = s * KS_ + c * 4 + kk;
                    const ulonglong2* wr =
                        reinterpret_cast<const ulonglong2*>(&sW[k * L_]);
                    ulonglong2 wA = wr[0], wB = wr[1], wC = wr[2], wD = wr[3];
                    uint64_t wq[8] = {wA.x, wA.y, wB.x, wB.y,
                                      wC.x, wC.y, wD.x, wD.y};
                    #pragma unroll
                    for (int m = 0; m < M_; ++m) {
                        float vk = (kk == 0) ? v[m].x : (kk == 1) ? v[m].y
                                 : (kk == 2) ? v[m].z : v[m].w;
                        uint64_t dv = dup_f32(vk);
                        #pragma unroll
                        for (int j = 0; j < 8; ++j) fma2(acc[m][j], dv, wq[j]);
                    }
                }
            }
        };

        #pragma unroll
        for (int m = 0; m < M_; ++m)
            #pragma unroll
            for (int j = 0; j < 8; ++j) acc[m][j] = 0ull;

        load_stage(0, 0); cp_commit();
        load_stage(1, 1); cp_commit();

        cp_wait<1>(); __syncwarp();
        compute_stage(0, 0);
        __syncwarp(); load_stage(2, 0); cp_commit();

        cp_wait<1>(); __syncwarp();
        compute_stage(1, 1);
        __syncwarp(); load_stage(3, 1); cp_commit();

        cp_wait<1>(); __syncwarp();
        compute_stage(2, 0);

        cp_wait<0>(); __syncwarp();
        compute_stage(3, 1);

        // epilogue: sign bits -> bucket
        #pragma unroll
        for (int m = 0; m < M_; ++m) {
            long gi = (long)t * TILE_ + w * ROWSW_ + 32 * m + l;
            unsigned b = 0;
            #pragma unroll
            for (int j = 0; j < 8; ++j) {
                float lo, hi;
                unpack2(acc[m][j], lo, hi);
                if (lo >= 0.0f) b |= 1u << (15 - 2 * j);
                if (hi >= 0.0f) b |= 1u << (14 - 2 * j);
            }
            if (outBuckets) {
                if (asInt) reinterpret_cast<int*>(outBuckets)[gi] = (int)b;
                else       outBuckets[gi] = (float)b;
            }
            if (outCounts) atomicAdd(&outCounts[b], 1.0f);
        }
        __syncwarp();   // all lanes done with buffers before next tile's loads
    }
}

// ---------------- launch ----------------
extern "C" void kernel_launch(void* const* d_in, const int* in_sizes, int n_in,
                              void* d_out, int out_size) {
    const float* items  = (const float*)d_in[0];
    const float* W      = (const float*)d_in[1];
    const float* counts = (const float*)d_in[2];
    const int n = in_sizes[0] / D_;

    float* out = (float*)d_out;
    float* outBuckets = nullptr;
    float* outCounts  = nullptr;
    int asInt = 0;

    if (out_size >= n + NB_) {           // concatenated (buckets, counts) as f32
        outBuckets = out;
        outCounts  = out + n;
    } else if (out_size == NB_) {        // counts only
        outCounts = out;
    } else {                             // buckets only -> int32
        outBuckets = out;
        asInt = 1;
    }

    if (outCounts)
        init_counts_kernel<<<(NB_ + 255) / 256, 256>>>(outCounts, counts, NB_);

    const int nTiles = n / TILE_;
    const int rem    = n - nTiles * TILE_;

    if (nTiles > 0)
        hash_counter_kernel<<<GRID_, BLOCK_>>>(items, W, outBuckets, outCounts,
                                               nTiles, asInt);
    if (rem > 0)
        hash_tail_kernel<<<(rem + 127) / 128, 128>>>(items, W, outBuckets,
                                                     outCounts, nTiles * TILE_,
                                                     n, asInt);
}

// round 7
// speedup vs baseline: 1.6070x; 1.0238x over previous
#include <cuda_runtime.h>
#include <cstdint>

// Problem constants
constexpr int D_   = 64;      // item dim
constexpr int L_   = 16;      // code length
constexpr int NB_  = 65536;   // buckets

// Tiling
constexpr int BLOCK_ = 64;               // 2 warps
constexpr int WARPS_ = BLOCK_ / 32;
constexpr int M_     = 4;                // items per thread
constexpr int ROWSW_ = 32 * M_;          // 128 rows per warp
constexpr int TILE_  = ROWSW_ * WARPS_;  // 256 rows per block-tile
constexpr int KS_    = 16;               // k per stage (64 B per row-stage)
constexpr int STF_   = ROWSW_ * KS_;     // 2048 floats per stage buffer (8 KB)
constexpr int GRID_  = 888;              // 148 SMs x 6 resident blocks

// ---------------- f32x2 helpers ----------------
__device__ __forceinline__ uint64_t dup_f32(float x) {
    uint64_t r; asm("mov.b64 %0, {%1, %1};" : "=l"(r) : "f"(x)); return r;
}
__device__ __forceinline__ void fma2(uint64_t& a, uint64_t b, uint64_t c) {
    asm("fma.rn.f32x2 %0, %1, %2, %0;" : "+l"(a) : "l"(b), "l"(c));
}
__device__ __forceinline__ void unpack2(uint64_t v, float& lo, float& hi) {
    asm("mov.b64 {%0, %1}, %2;" : "=f"(lo), "=f"(hi) : "l"(v));
}
__device__ __forceinline__ void cp_async16(void* d, const void* s) {
    unsigned a = (unsigned)__cvta_generic_to_shared(d);
    asm volatile("cp.async.cg.shared.global [%0], [%1], 16;" :: "r"(a), "l"(s));
}
__device__ __forceinline__ void cp_commit() {
    asm volatile("cp.async.commit_group;" ::: "memory");
}
template<int N>
__device__ __forceinline__ void cp_wait() {
    asm volatile("cp.async.wait_group %0;" :: "n"(N) : "memory");
}

// ---------------- counts init ----------------
__global__ void init_counts_kernel(float* __restrict__ outCounts,
                                   const float* __restrict__ counts, int nb) {
    int i = blockIdx.x * blockDim.x + threadIdx.x;
    if (i < nb) outCounts[i] = counts[i];
}

// ---------------- tail kernel (n % TILE_ items; usually 0 blocks) ----------
__global__ void hash_tail_kernel(const float* __restrict__ items,
                                 const float* __restrict__ W,
                                 float* __restrict__ outBuckets,
                                 float* __restrict__ outCounts,
                                 int start, int n, int asInt) {
    int gi = start + blockIdx.x * blockDim.x + threadIdx.x;
    if (gi >= n) return;
    const float* row = items + (size_t)gi * D_;
    float dot[L_];
    #pragma unroll
    for (int j = 0; j < L_; ++j) dot[j] = 0.0f;
    for (int k = 0; k < D_; ++k) {
        float v = row[k];
        #pragma unroll
        for (int j = 0; j < L_; ++j) dot[j] = fmaf(v, W[k * L_ + j], dot[j]);
    }
    unsigned b = 0;
    #pragma unroll
    for (int j = 0; j < L_; ++j)
        if (dot[j] >= 0.0f) b |= 1u << (L_ - 1 - j);
    if (outBuckets) {
        if (asInt) reinterpret_cast<int*>(outBuckets)[gi] = (int)b;
        else       outBuckets[gi] = (float)b;
    }
    if (outCounts) atomicAdd(&outCounts[b], 1.0f);
}

// ---------------- main kernel ----------------
__global__ __launch_bounds__(BLOCK_)
void hash_counter_kernel(const float* __restrict__ items,
                         const float* __restrict__ W,
                         float* __restrict__ outBuckets,
                         float* __restrict__ outCounts,
                         int nTiles, int asInt) {
    // Per warp: two 8 KB stage buffers. Row r (0..127) stage data: 16 floats,
    // 16B-chunk c stored at unit (r*4 + (c ^ ((r>>1)&3))).
    // Conflict-free for coalesced stores and strided consumer reads.
    __shared__ __align__(128) float sIt[WARPS_][2][STF_];
    __shared__ __align__(16)  float sW[D_ * L_];

    const int tid = threadIdx.x;
    const int w   = tid >> 5;
    const int l   = tid & 31;
    const long bid = blockIdx.x;

    const long nMy = (nTiles - bid + GRID_ - 1) / GRID_;   // tiles for this block
    if (nMy <= 0) return;

    for (int i = tid; i < D_ * L_; i += BLOCK_) sW[i] = W[i];
    __syncthreads();

    // ---- hoisted loader constants ----
    const int scolL = (l & 3) ^ ((l >> 3) & 3);
    float* const smL0 = &sIt[w][0][(l >> 2) * KS_ + scolL * 4];

    // ---- hoisted consumer constants ----
    char* const cb0 = (char*)&sIt[w][0][0];
    unsigned coff[M_];
    {
        const unsigned z = ((unsigned)(l >> 1) & 3u) << 4;
        #pragma unroll
        for (int m = 0; m < M_; ++m)
            coff[m] = (unsigned)(2048 * m + 64 * l) + z;
    }

    // ---- cross-tile load cursor ----
    const size_t tileStride = (size_t)GRID_ * TILE_ * D_;
    const size_t rowOff = (size_t)(w * ROWSW_ + (l >> 2)) * D_ + (l & 3) * 4;
    const float* pL = items + (size_t)bid * TILE_ * D_ + rowOff;
    int  sL = 0;                 // stage-within-tile of the load cursor
    long qL = 0;                 // global stage index of the load cursor
    const long qTot = nMy * 4;

    auto issue = [&](int buf) {
        if (qL < qTot) {
            float* sm = smL0 + buf * STF_;
            #pragma unroll
            for (int i = 0; i < 16; ++i)
                cp_async16(sm + i * 128, pL + (size_t)i * 8 * D_);
            if (sL == 3) { sL = 0; pL += tileStride - 3 * KS_; }
            else         { ++sL;  pL += KS_; }
            ++qL;
        }
        cp_commit();             // empty groups at stream end are fine
    };

    auto compute_stage = [&](int s, int buf, uint64_t (&acc)[M_][8]) {
        const char* cbuf = cb0 + buf * (STF_ * 4);
        #pragma unroll
        for (int c = 0; c < 4; ++c) {
            float4 v[M_];
            #pragma unroll
            for (int m = 0; m < M_; ++m)
                v[m] = *reinterpret_cast<const float4*>(
                           cbuf + (coff[m] ^ (unsigned)(c << 4)));
            #pragma unroll
            for (int kk = 0; kk < 4; ++kk) {
                const int k = s * KS_ + c * 4 + kk;
                const ulonglong2* wr =
                    reinterpret_cast<const ulonglong2*>(&sW[k * L_]);
                ulonglong2 wA = wr[0], wB = wr[1], wC = wr[2], wD = wr[3];
                uint64_t wq[8] = {wA.x, wA.y, wB.x, wB.y, wC.x, wC.y, wD.x, wD.y};
                #pragma unroll
                for (int m = 0; m < M_; ++m) {
                    float vk = (kk == 0) ? v[m].x : (kk == 1) ? v[m].y
                             : (kk == 2) ? v[m].z : v[m].w;
                    uint64_t dv = dup_f32(vk);
                    #pragma unroll
                    for (int j = 0; j < 8; ++j) fma2(acc[m][j], dv, wq[j]);
                }
            }
        }
    };

    // Prologue: stages 0 and 1 of the first tile
    issue(0);
    issue(1);

    uint64_t acc[M_][8];
    long tAct = bid;

    for (long tt = 0; tt < nMy; ++tt) {
        #pragma unroll
        for (int m = 0; m < M_; ++m)
            #pragma unroll
            for (int j = 0; j < 8; ++j) acc[m][j] = 0ull;

        // Stage s: wait for its group, compute, then refill its buffer with
        // stage s+2 of the linearized stream (possibly next tile's stage 0/1).
        cp_wait<1>(); __syncwarp();
        compute_stage(0, 0, acc);
        __syncwarp(); issue(0);

        cp_wait<1>(); __syncwarp();
        compute_stage(1, 1, acc);
        __syncwarp(); issue(1);

        cp_wait<1>(); __syncwarp();
        compute_stage(2, 0, acc);
        __syncwarp(); issue(0);

        cp_wait<1>(); __syncwarp();
        compute_stage(3, 1, acc);
        __syncwarp(); issue(1);

        // Epilogue overlaps the already-issued next-tile loads.
        #pragma unroll
        for (int m = 0; m < M_; ++m) {
            long gi = tAct * TILE_ + w * ROWSW_ + 32 * m + l;
            unsigned b = 0;
            #pragma unroll
            for (int j = 0; j < 8; ++j) {
                float lo, hi;
                unpack2(acc[m][j], lo, hi);
                if (lo >= 0.0f) b |= 1u << (15 - 2 * j);
                if (hi >= 0.0f) b |= 1u << (14 - 2 * j);
            }
            if (outBuckets) {
                if (asInt) reinterpret_cast<int*>(outBuckets)[gi] = (int)b;
                else       outBuckets[gi] = (float)b;
            }
            if (outCounts) atomicAdd(&outCounts[b], 1.0f);
        }
        tAct += GRID_;
    }
}

// ---------------- launch ----------------
extern "C" void kernel_launch(void* const* d_in, const int* in_sizes, int n_in,
                              void* d_out, int out_size) {
    const float* items  = (const float*)d_in[0];
    const float* W      = (const float*)d_in[1];
    const float* counts = (const float*)d_in[2];
    const int n = in_sizes[0] / D_;

    float* out = (float*)d_out;
    float* outBuckets = nullptr;
    float* outCounts  = nullptr;
    int asInt = 0;

    if (out_size >= n + NB_) {           // concatenated (buckets, counts) as f32
        outBuckets = out;
        outCounts  = out + n;
    } else if (out_size == NB_) {        // counts only
        outCounts = out;
    } else {                             // buckets only -> int32
        outBuckets = out;
        asInt = 1;
    }

    if (outCounts)
        init_counts_kernel<<<(NB_ + 255) / 256, 256>>>(outCounts, counts, NB_);

    const int nTiles = n / TILE_;
    const int rem    = n - nTiles * TILE_;

    if (nTiles > 0)
        hash_counter_kernel<<<GRID_, BLOCK_>>>(items, W, outBuckets, outCounts,
                                               nTiles, asInt);
    if (rem > 0)
        hash_tail_kernel<<<(rem + 127) / 128, 128>>>(items, W, outBuckets,
                                                     outCounts, nTiles * TILE_,
                                                     n, asInt);
}